// round 1
// baseline (speedup 1.0000x reference)
#include <cuda_runtime.h>

#define NN 20000      // nodes
#define NE 320000     // edges
#define DN 128        // d_node
#define DE 128        // d_edge
#define DA 16         // d_attr
#define NH 256        // hidden
#define NG 64         // graphs
// W1 K layout: [xr 0:128 | nf_r 128:256 | xc 256:384 | nf_c 384:512 | attr 512:528]
#define K1TOT 528

// ---------------- scratch (device globals; no allocation allowed) ----------------
__device__ float g_nproj[NN * 8];            // a_r,a_c,u_r,u_c,rd_r,rd_c (pad 8)
__device__ float g_logit[NE];
__device__ float g_w[NE];
__device__ float g_nmax[NN];
__device__ float g_nsum[NN];
__device__ float g_nodefeat[NN * DE];
__device__ float g_hidden[81920000];         // NE*NH fp32 (~328MB)
__device__ float g_cand[40960000];           // NE*DE fp32 (~164MB)
__device__ float g_rlogit[NE];
__device__ float g_rw[NE];
__device__ float g_gmax[NG];
__device__ float g_gsum[NG];
__device__ float g_graphfeat[NG * DE];

// ---------------- helpers ----------------
__device__ __forceinline__ float dot4(float4 a, float4 b) {
    return fmaf(a.x, b.x, fmaf(a.y, b.y, fmaf(a.z, b.z, a.w * b.w)));
}

__device__ __forceinline__ float wred(float v) {
    v += __shfl_xor_sync(0xffffffffu, v, 16);
    v += __shfl_xor_sync(0xffffffffu, v, 8);
    v += __shfl_xor_sync(0xffffffffu, v, 4);
    v += __shfl_xor_sync(0xffffffffu, v, 2);
    v += __shfl_xor_sync(0xffffffffu, v, 1);
    return v;
}

__device__ __forceinline__ void atomicMaxF(float* addr, float v) {
    int* ia = (int*)addr;
    int old = __float_as_int(*addr);
    while (__int_as_float(old) < v) {
        int prev = atomicCAS(ia, old, __float_as_int(v));
        if (prev == old) break;
        old = prev;
    }
}

// ---------------- init scratch ----------------
__global__ void k_init() {
    int i = blockIdx.x * 256 + threadIdx.x;
    if (i < NN * DE) g_nodefeat[i] = 0.f;
    if (i < NN) { g_nmax[i] = -1e30f; g_nsum[i] = 0.f; }
    if (i < NG * DE) g_graphfeat[i] = 0.f;
    if (i < NG) { g_gmax[i] = -1e30f; g_gsum[i] = 0.f; }
}

// ---------------- per-node scalar projections (rank-1 weight parts) ----------------
__global__ void k_nodeproj(const float* __restrict__ x, const float* __restrict__ Wagg,
                           const float* __restrict__ Wupd, const float* __restrict__ Wread) {
    int warp = threadIdx.x >> 5, lane = threadIdx.x & 31;
    int n = blockIdx.x * 8 + warp;
    if (n >= NN) return;
    float4 xv = ((const float4*)x)[n * 32 + lane];
    const float4* wa = (const float4*)Wagg;
    const float4* wu = (const float4*)Wupd;
    const float4* wr = (const float4*)Wread;
    float s0 = dot4(xv, wa[lane]);
    float s1 = dot4(xv, wa[32 + lane]);
    float s2 = dot4(xv, wu[lane]);
    float s3 = dot4(xv, wu[32 + lane]);
    float s4 = dot4(xv, wr[lane]);
    float s5 = dot4(xv, wr[32 + lane]);
    s0 = wred(s0); s1 = wred(s1); s2 = wred(s2);
    s3 = wred(s3); s4 = wred(s4); s5 = wred(s5);
    if (lane == 0) {
        g_nproj[n * 8 + 0] = s0; g_nproj[n * 8 + 1] = s1;
        g_nproj[n * 8 + 2] = s2; g_nproj[n * 8 + 3] = s3;
        g_nproj[n * 8 + 4] = s4; g_nproj[n * 8 + 5] = s5;
    }
}

// ---------------- aggregation attention logits + segment max ----------------
__global__ void k_agglogit(const float* __restrict__ hef, const float* __restrict__ attr,
                           const int* __restrict__ ei, const float* __restrict__ Wagg,
                           const float* __restrict__ bagg) {
    int warp = threadIdx.x >> 5, lane = threadIdx.x & 31;
    int e = blockIdx.x * 8 + warp;
    if (e >= NE) return;
    int r = ei[e], c = ei[NE + e];
    float4 h4 = ((const float4*)hef)[e * 32 + lane];
    float4 wh = *(const float4*)&Wagg[272 + lane * 4];
    float p = dot4(h4, wh);
    if (lane < 4) {
        float4 a4 = ((const float4*)attr)[e * 4 + lane];
        float4 wa = *(const float4*)&Wagg[256 + lane * 4];
        p += dot4(a4, wa);
    }
    p = wred(p);
    if (lane == 0) {
        float logit = p + g_nproj[r * 8 + 0] + g_nproj[c * 8 + 1] + bagg[0];
        g_logit[e] = logit;
        atomicMaxF(&g_nmax[c], logit);
    }
}

// ---------------- exp + segment sum ----------------
__global__ void k_expw(const int* __restrict__ ei) {
    int e = blockIdx.x * 256 + threadIdx.x;
    if (e >= NE) return;
    int c = ei[NE + e];
    float w = expf(g_logit[e] - g_nmax[c]);
    g_w[e] = w;
    atomicAdd(&g_nsum[c], w);
}

// ---------------- normalize + scatter w*h into node_feat ----------------
__global__ void k_nscatter(const float* __restrict__ hef, const int* __restrict__ ei) {
    int warp = threadIdx.x >> 5, lane = threadIdx.x & 31;
    int e = blockIdx.x * 8 + warp;
    if (e >= NE) return;
    int c = ei[NE + e];
    float wn = g_w[e] / (g_nsum[c] + 1e-16f);
    float4 h4 = ((const float4*)hef)[e * 32 + lane];
    float* p = &g_nodefeat[c * 128 + lane * 4];
    atomicAdd(p + 0, wn * h4.x);
    atomicAdd(p + 1, wn * h4.y);
    atomicAdd(p + 2, wn * h4.z);
    atomicAdd(p + 3, wn * h4.w);
}

// ---------------- GEMM1: hidden = relu(gather(emb_in) @ W1 + b1) ----------------
__global__ void __launch_bounds__(256, 2)
k_gemm1(const float* __restrict__ x, const float* __restrict__ attr,
        const int* __restrict__ ei, const float* __restrict__ W1,
        const float* __restrict__ b1) {
    __shared__ float As[2][8][128];
    __shared__ float Bs[2][8][128];
    __shared__ int srol[128], scol[128];
    int t = threadIdx.x;
    int me0 = blockIdx.x * 128, hn0 = blockIdx.y * 128;
    if (t < 128) srol[t] = ei[me0 + t];
    else scol[t - 128] = ei[NE + me0 + t - 128];
    __syncthreads();

    int am = t >> 1, ak = (t & 1) * 4;
    int bk = t >> 5, bn = (t & 31) * 4;

    auto ldA = [&](int k0) -> float4 {
        int k = k0 + ak;
        if (k < 128) return *(const float4*)&x[srol[am] * 128 + k];
        if (k < 256) return *(const float4*)&g_nodefeat[srol[am] * 128 + (k - 128)];
        if (k < 384) return *(const float4*)&x[scol[am] * 128 + (k - 256)];
        if (k < 512) return *(const float4*)&g_nodefeat[scol[am] * 128 + (k - 384)];
        return *(const float4*)&attr[(me0 + am) * 16 + (k - 512)];
    };

    float4 aR = ldA(0);
    float4 bR = *(const float4*)&W1[bk * 256 + hn0 + bn];
    As[0][ak + 0][am] = aR.x; As[0][ak + 1][am] = aR.y;
    As[0][ak + 2][am] = aR.z; As[0][ak + 3][am] = aR.w;
    *(float4*)&Bs[0][bk][bn] = bR;
    __syncthreads();

    float acc[8][8];
#pragma unroll
    for (int i = 0; i < 8; i++)
#pragma unroll
        for (int j = 0; j < 8; j++) acc[i][j] = 0.f;

    int ty = t >> 4, tx = t & 15;
    for (int kt = 0; kt < 66; ++kt) {
        int cur = kt & 1;
        if (kt < 65) {
            aR = ldA((kt + 1) * 8);
            bR = *(const float4*)&W1[((kt + 1) * 8 + bk) * 256 + hn0 + bn];
        }
#pragma unroll
        for (int kk = 0; kk < 8; kk++) {
            float a[8], b[8];
            *(float4*)&a[0] = *(float4*)&As[cur][kk][ty * 8];
            *(float4*)&a[4] = *(float4*)&As[cur][kk][ty * 8 + 4];
            *(float4*)&b[0] = *(float4*)&Bs[cur][kk][tx * 8];
            *(float4*)&b[4] = *(float4*)&Bs[cur][kk][tx * 8 + 4];
#pragma unroll
            for (int i = 0; i < 8; i++)
#pragma unroll
                for (int j = 0; j < 8; j++) acc[i][j] = fmaf(a[i], b[j], acc[i][j]);
        }
        if (kt < 65) {
            int nb = cur ^ 1;
            As[nb][ak + 0][am] = aR.x; As[nb][ak + 1][am] = aR.y;
            As[nb][ak + 2][am] = aR.z; As[nb][ak + 3][am] = aR.w;
            *(float4*)&Bs[nb][bk][bn] = bR;
        }
        __syncthreads();
    }

#pragma unroll
    for (int i = 0; i < 8; i++) {
        int m = me0 + ty * 8 + i;
#pragma unroll
        for (int j0 = 0; j0 < 8; j0 += 4) {
            int h = hn0 + tx * 8 + j0;
            float4 v;
            v.x = fmaxf(acc[i][j0 + 0] + b1[h + 0], 0.f);
            v.y = fmaxf(acc[i][j0 + 1] + b1[h + 1], 0.f);
            v.z = fmaxf(acc[i][j0 + 2] + b1[h + 2], 0.f);
            v.w = fmaxf(acc[i][j0 + 3] + b1[h + 3], 0.f);
            *(float4*)&g_hidden[(size_t)m * 256 + h] = v;
        }
    }
}

// ---------------- GEMM2: cand = hidden @ W2 + b2 ----------------
__global__ void __launch_bounds__(256, 2)
k_gemm2(const float* __restrict__ W2, const float* __restrict__ b2) {
    __shared__ float As[2][8][128];
    __shared__ float Bs[2][8][128];
    int t = threadIdx.x;
    int me0 = blockIdx.x * 128;

    int am = t >> 1, ak = (t & 1) * 4;
    int bk = t >> 5, bn = (t & 31) * 4;

    float4 aR = *(const float4*)&g_hidden[(size_t)(me0 + am) * 256 + ak];
    float4 bR = *(const float4*)&W2[bk * 128 + bn];
    As[0][ak + 0][am] = aR.x; As[0][ak + 1][am] = aR.y;
    As[0][ak + 2][am] = aR.z; As[0][ak + 3][am] = aR.w;
    *(float4*)&Bs[0][bk][bn] = bR;
    __syncthreads();

    float acc[8][8];
#pragma unroll
    for (int i = 0; i < 8; i++)
#pragma unroll
        for (int j = 0; j < 8; j++) acc[i][j] = 0.f;

    int ty = t >> 4, tx = t & 15;
    for (int kt = 0; kt < 32; ++kt) {
        int cur = kt & 1;
        if (kt < 31) {
            aR = *(const float4*)&g_hidden[(size_t)(me0 + am) * 256 + (kt + 1) * 8 + ak];
            bR = *(const float4*)&W2[((kt + 1) * 8 + bk) * 128 + bn];
        }
#pragma unroll
        for (int kk = 0; kk < 8; kk++) {
            float a[8], b[8];
            *(float4*)&a[0] = *(float4*)&As[cur][kk][ty * 8];
            *(float4*)&a[4] = *(float4*)&As[cur][kk][ty * 8 + 4];
            *(float4*)&b[0] = *(float4*)&Bs[cur][kk][tx * 8];
            *(float4*)&b[4] = *(float4*)&Bs[cur][kk][tx * 8 + 4];
#pragma unroll
            for (int i = 0; i < 8; i++)
#pragma unroll
                for (int j = 0; j < 8; j++) acc[i][j] = fmaf(a[i], b[j], acc[i][j]);
        }
        if (kt < 31) {
            int nb = cur ^ 1;
            As[nb][ak + 0][am] = aR.x; As[nb][ak + 1][am] = aR.y;
            As[nb][ak + 2][am] = aR.z; As[nb][ak + 3][am] = aR.w;
            *(float4*)&Bs[nb][bk][bn] = bR;
        }
        __syncthreads();
    }

#pragma unroll
    for (int i = 0; i < 8; i++) {
        int m = me0 + ty * 8 + i;
#pragma unroll
        for (int j0 = 0; j0 < 8; j0 += 4) {
            int h = tx * 8 + j0;
            float4 v;
            v.x = acc[i][j0 + 0] + b2[h + 0];
            v.y = acc[i][j0 + 1] + b2[h + 1];
            v.z = acc[i][j0 + 2] + b2[h + 2];
            v.w = acc[i][j0 + 3] + b2[h + 3];
            *(float4*)&g_cand[(size_t)m * 128 + h] = v;
        }
    }
}

// ---------------- gate + edge_feat + readout logits + segment max ----------------
__global__ void k_gate(const float* __restrict__ hef, const float* __restrict__ attr,
                       const int* __restrict__ ei, const int* __restrict__ batch,
                       const float* __restrict__ Wupd, const float* __restrict__ bupd,
                       const float* __restrict__ Wread, const float* __restrict__ bread,
                       float* __restrict__ out) {
    int warp = threadIdx.x >> 5, lane = threadIdx.x & 31;
    int e = blockIdx.x * 8 + warp;
    if (e >= NE) return;
    int r = ei[e], c = ei[NE + e];
    float4 cd = ((const float4*)g_cand)[e * 32 + lane];
    float4 hh = ((const float4*)hef)[e * 32 + lane];
    float4 wuc = *(const float4*)&Wupd[400 + lane * 4];
    float4 wuh = *(const float4*)&Wupd[272 + lane * 4];
    float p = dot4(cd, wuc) + dot4(hh, wuh);
    float4 a4 = make_float4(0.f, 0.f, 0.f, 0.f);
    if (lane < 4) {
        a4 = ((const float4*)attr)[e * 4 + lane];
        float4 wua = *(const float4*)&Wupd[256 + lane * 4];
        p += dot4(a4, wua);
    }
    p = wred(p);
    float gv = p + g_nproj[r * 8 + 2] + g_nproj[c * 8 + 3] + bupd[0];
    float g = 1.f / (1.f + expf(-gv));
    float4 ef;
    ef.x = fmaf(g, cd.x - hh.x, hh.x);
    ef.y = fmaf(g, cd.y - hh.y, hh.y);
    ef.z = fmaf(g, cd.z - hh.z, hh.z);
    ef.w = fmaf(g, cd.w - hh.w, hh.w);
    ((float4*)out)[e * 32 + lane] = ef;

    float4 wre = *(const float4*)&Wread[256 + lane * 4];
    float q = dot4(ef, wre);
    if (lane < 4) {
        float4 wra = *(const float4*)&Wread[384 + lane * 4];
        q += dot4(a4, wra);
    }
    q = wred(q);
    if (lane == 0) {
        float rl = q + g_nproj[r * 8 + 4] + g_nproj[c * 8 + 5] + bread[0];
        g_rlogit[e] = rl;
        atomicMaxF(&g_gmax[batch[r]], rl);
    }
}

// ---------------- readout exp + segment sum (smem aggregated) ----------------
__global__ void k_rexp(const int* __restrict__ ei, const int* __restrict__ batch) {
    __shared__ float ss[NG];
    int t = threadIdx.x;
    if (t < NG) ss[t] = 0.f;
    __syncthreads();
    int e = blockIdx.x * 256 + t;
    if (e < NE) {
        int gi = batch[ei[e]];
        float rw = expf(g_rlogit[e] - g_gmax[gi]);
        g_rw[e] = rw;
        atomicAdd(&ss[gi], rw);
    }
    __syncthreads();
    if (t < NG && ss[t] != 0.f) atomicAdd(&g_gsum[t], ss[t]);
}

// ---------------- readout scatter into graph_feat (smem 64x128 tile) ----------------
__global__ void k_rscatter(const int* __restrict__ ei, const int* __restrict__ batch,
                           const float* __restrict__ out) {
    __shared__ float sacc[NG * DE];   // 32 KB
    int t = threadIdx.x;
    for (int i = t; i < NG * DE; i += 256) sacc[i] = 0.f;
    __syncthreads();
    int warp = t >> 5, lane = t & 31;
    for (int e = blockIdx.x * 8 + warp; e < NE; e += gridDim.x * 8) {
        int gi = batch[ei[e]];
        float rn = g_rw[e] / (g_gsum[gi] + 1e-16f);
        float4 ef = ((const float4*)out)[e * 32 + lane];
        float* p = &sacc[gi * 128 + lane * 4];
        atomicAdd(p + 0, rn * ef.x);
        atomicAdd(p + 1, rn * ef.y);
        atomicAdd(p + 2, rn * ef.z);
        atomicAdd(p + 3, rn * ef.w);
    }
    __syncthreads();
    for (int i = t; i < NG * DE; i += 256)
        if (sacc[i] != 0.f) atomicAdd(&g_graphfeat[i], sacc[i]);
}

// ---------------- confidence ----------------
__global__ void k_conf(const float* __restrict__ Wscore, const float* __restrict__ bscore,
                       float* __restrict__ out) {
    int g = blockIdx.x, t = threadIdx.x;
    float v = g_graphfeat[g * 128 + t] * Wscore[t];
    v = wred(v);
    __shared__ float sm[4];
    if ((t & 31) == 0) sm[t >> 5] = v;
    __syncthreads();
    if (t == 0) {
        float s = sm[0] + sm[1] + sm[2] + sm[3] + bscore[0];
        out[(size_t)NE * DE + g] = 1.f / (1.f + expf(-s));
    }
}

// ---------------- launch ----------------
extern "C" void kernel_launch(void* const* d_in, const int* in_sizes, int n_in,
                              void* d_out, int out_size) {
    const float* x      = (const float*)d_in[0];
    const float* hef    = (const float*)d_in[1];
    const float* attr   = (const float*)d_in[2];
    const int*   ei     = (const int*)d_in[3];
    const int*   batch  = (const int*)d_in[4];
    // d_in[5] = num_graphs (compile-time NG)
    const float* Wagg   = (const float*)d_in[6];
    const float* bagg   = (const float*)d_in[7];
    const float* W1     = (const float*)d_in[8];
    const float* b1     = (const float*)d_in[9];
    const float* W2     = (const float*)d_in[10];
    const float* b2     = (const float*)d_in[11];
    const float* Wupd   = (const float*)d_in[12];
    const float* bupd   = (const float*)d_in[13];
    const float* Wread  = (const float*)d_in[14];
    const float* bread  = (const float*)d_in[15];
    const float* Wscore = (const float*)d_in[16];
    const float* bscore = (const float*)d_in[17];
    float* out = (float*)d_out;

    k_init<<<(NN * DE + 255) / 256, 256>>>();
    k_nodeproj<<<(NN + 7) / 8, 256>>>(x, Wagg, Wupd, Wread);
    k_agglogit<<<NE / 8, 256>>>(hef, attr, ei, Wagg, bagg);
    k_expw<<<NE / 256, 256>>>(ei);
    k_nscatter<<<NE / 8, 256>>>(hef, ei);
    k_gemm1<<<dim3(NE / 128, NH / 128), 256>>>(x, attr, ei, W1, b1);
    k_gemm2<<<NE / 128, 256>>>(W2, b2);
    k_gate<<<NE / 8, 256>>>(hef, attr, ei, batch, Wupd, bupd, Wread, bread, out);
    k_rexp<<<NE / 256, 256>>>(ei, batch);
    k_rscatter<<<296, 256>>>(ei, batch, out);
    k_conf<<<NG, 128>>>(Wscore, bscore, out);
}

// round 2
// speedup vs baseline: 1.1429x; 1.1429x over previous
#include <cuda_runtime.h>
#include <stdint.h>

#define NN 20000      // nodes
#define NE 320000     // edges
#define DN 128        // d_node
#define DE 128        // d_edge
#define DA 16         // d_attr
#define NH 256        // hidden
#define NG 64         // graphs
#define K1TOT 528

// ---------------- scratch (device globals; no allocation allowed) ----------------
__device__ float g_nproj[NN * 8];            // a_r,a_c,u_r,u_c,rd_r,rd_c (pad 8)
__device__ float g_logit[NE];
__device__ float g_w[NE];
__device__ float g_nmax[NN];
__device__ float g_nsum[NN];
__device__ float g_nodefeat[NN * DE];
__device__ float g_hidden[81920000];         // NE*NH fp32 (~328MB)
__device__ float g_cand[40960000];           // NE*DE fp32 (~164MB)
__device__ float g_rlogit[NE];
__device__ float g_rw[NE];
__device__ float g_gmax[NG];
__device__ float g_gsum[NG];
__device__ float g_graphfeat[NG * DE];

// ---------------- helpers ----------------
__device__ __forceinline__ float dot4(float4 a, float4 b) {
    return fmaf(a.x, b.x, fmaf(a.y, b.y, fmaf(a.z, b.z, a.w * b.w)));
}

__device__ __forceinline__ float wred(float v) {
    v += __shfl_xor_sync(0xffffffffu, v, 16);
    v += __shfl_xor_sync(0xffffffffu, v, 8);
    v += __shfl_xor_sync(0xffffffffu, v, 4);
    v += __shfl_xor_sync(0xffffffffu, v, 2);
    v += __shfl_xor_sync(0xffffffffu, v, 1);
    return v;
}

__device__ __forceinline__ void atomicMaxF(float* addr, float v) {
    int* ia = (int*)addr;
    int old = __float_as_int(*addr);
    while (__int_as_float(old) < v) {
        int prev = atomicCAS(ia, old, __float_as_int(v));
        if (prev == old) break;
        old = prev;
    }
}

__device__ __forceinline__ uint32_t f2tf(float f) {
    uint32_t u;
    asm("cvt.rna.tf32.f32 %0, %1;" : "=r"(u) : "f"(f));
    return u;
}

__device__ __forceinline__ void mma8(float* c, const uint32_t* a, uint32_t b0, uint32_t b1) {
    asm volatile("mma.sync.aligned.m16n8k8.row.col.f32.tf32.tf32.f32 "
        "{%0,%1,%2,%3}, {%4,%5,%6,%7}, {%8,%9}, {%0,%1,%2,%3};"
        : "+f"(c[0]), "+f"(c[1]), "+f"(c[2]), "+f"(c[3])
        : "r"(a[0]), "r"(a[1]), "r"(a[2]), "r"(a[3]), "r"(b0), "r"(b1));
}

// ---------------- init scratch ----------------
__global__ void k_init() {
    int i = blockIdx.x * 256 + threadIdx.x;
    if (i < NN * DE) g_nodefeat[i] = 0.f;
    if (i < NN) { g_nmax[i] = -1e30f; g_nsum[i] = 0.f; }
    if (i < NG * DE) g_graphfeat[i] = 0.f;
    if (i < NG) { g_gmax[i] = -1e30f; g_gsum[i] = 0.f; }
}

// ---------------- per-node scalar projections ----------------
__global__ void k_nodeproj(const float* __restrict__ x, const float* __restrict__ Wagg,
                           const float* __restrict__ Wupd, const float* __restrict__ Wread) {
    int warp = threadIdx.x >> 5, lane = threadIdx.x & 31;
    int n = blockIdx.x * 8 + warp;
    if (n >= NN) return;
    float4 xv = ((const float4*)x)[n * 32 + lane];
    const float4* wa = (const float4*)Wagg;
    const float4* wu = (const float4*)Wupd;
    const float4* wr = (const float4*)Wread;
    float s0 = dot4(xv, wa[lane]);
    float s1 = dot4(xv, wa[32 + lane]);
    float s2 = dot4(xv, wu[lane]);
    float s3 = dot4(xv, wu[32 + lane]);
    float s4 = dot4(xv, wr[lane]);
    float s5 = dot4(xv, wr[32 + lane]);
    s0 = wred(s0); s1 = wred(s1); s2 = wred(s2);
    s3 = wred(s3); s4 = wred(s4); s5 = wred(s5);
    if (lane == 0) {
        g_nproj[n * 8 + 0] = s0; g_nproj[n * 8 + 1] = s1;
        g_nproj[n * 8 + 2] = s2; g_nproj[n * 8 + 3] = s3;
        g_nproj[n * 8 + 4] = s4; g_nproj[n * 8 + 5] = s5;
    }
}

// ---------------- aggregation attention logits + segment max ----------------
__global__ void k_agglogit(const float* __restrict__ hef, const float* __restrict__ attr,
                           const int* __restrict__ ei, const float* __restrict__ Wagg,
                           const float* __restrict__ bagg) {
    int warp = threadIdx.x >> 5, lane = threadIdx.x & 31;
    int e = blockIdx.x * 8 + warp;
    if (e >= NE) return;
    int r = ei[e], c = ei[NE + e];
    float4 h4 = ((const float4*)hef)[e * 32 + lane];
    float4 wh = *(const float4*)&Wagg[272 + lane * 4];
    float p = dot4(h4, wh);
    if (lane < 4) {
        float4 a4 = ((const float4*)attr)[e * 4 + lane];
        float4 wa = *(const float4*)&Wagg[256 + lane * 4];
        p += dot4(a4, wa);
    }
    p = wred(p);
    if (lane == 0) {
        float logit = p + g_nproj[r * 8 + 0] + g_nproj[c * 8 + 1] + bagg[0];
        g_logit[e] = logit;
        atomicMaxF(&g_nmax[c], logit);
    }
}

// ---------------- exp + segment sum ----------------
__global__ void k_expw(const int* __restrict__ ei) {
    int e = blockIdx.x * 256 + threadIdx.x;
    if (e >= NE) return;
    int c = ei[NE + e];
    float w = expf(g_logit[e] - g_nmax[c]);
    g_w[e] = w;
    atomicAdd(&g_nsum[c], w);
}

// ---------------- normalize + scatter w*h into node_feat ----------------
__global__ void k_nscatter(const float* __restrict__ hef, const int* __restrict__ ei) {
    int warp = threadIdx.x >> 5, lane = threadIdx.x & 31;
    int e = blockIdx.x * 8 + warp;
    if (e >= NE) return;
    int c = ei[NE + e];
    float wn = g_w[e] / (g_nsum[c] + 1e-16f);
    float4 h4 = ((const float4*)hef)[e * 32 + lane];
    float* p = &g_nodefeat[c * 128 + lane * 4];
    atomicAdd(p + 0, wn * h4.x);
    atomicAdd(p + 1, wn * h4.y);
    atomicAdd(p + 2, wn * h4.z);
    atomicAdd(p + 3, wn * h4.w);
}

// ==================== GEMM1 (tensor, 3xTF32): hidden = relu(emb_in @ W1 + b1) ====================
// Block tile 128x128, 8 warps as 4(M) x 2(N), warp tile 32x64, mma m16n8k8.
__global__ void __launch_bounds__(256)
k_gemm1(const float* __restrict__ x, const float* __restrict__ attr,
        const int* __restrict__ ei, const float* __restrict__ W1,
        const float* __restrict__ b1) {
    __shared__ uint32_t AsH[2][8][136], AsL[2][8][136];
    __shared__ uint32_t BsH[2][8][136], BsL[2][8][136];
    __shared__ int srol[128], scol[128];
    int t = threadIdx.x;
    int me0 = blockIdx.x * 128, hn0 = blockIdx.y * 128;
    if (t < 128) srol[t] = ei[me0 + t];
    else scol[t - 128] = ei[NE + me0 + t - 128];
    __syncthreads();

    int am = t >> 1, ak = (t & 1) * 4;
    int bk = t >> 5, bn = (t & 31) * 4;

    auto ldA = [&](int k0) -> float4 {
        int k = k0 + ak;
        if (k < 128) return *(const float4*)&x[srol[am] * 128 + k];
        if (k < 256) return *(const float4*)&g_nodefeat[srol[am] * 128 + (k - 128)];
        if (k < 384) return *(const float4*)&x[scol[am] * 128 + (k - 256)];
        if (k < 512) return *(const float4*)&g_nodefeat[scol[am] * 128 + (k - 384)];
        return *(const float4*)&attr[(me0 + am) * 16 + (k - 512)];
    };

    auto stage = [&](int buf, float4 av, float4 bv) {
        float fa[4] = {av.x, av.y, av.z, av.w};
        float fb[4] = {bv.x, bv.y, bv.z, bv.w};
#pragma unroll
        for (int i = 0; i < 4; i++) {
            uint32_t h = f2tf(fa[i]);
            AsH[buf][ak + i][am] = h;
            AsL[buf][ak + i][am] = f2tf(fa[i] - __uint_as_float(h));
            uint32_t hb = f2tf(fb[i]);
            BsH[buf][bk][bn + i] = hb;
            BsL[buf][bk][bn + i] = f2tf(fb[i] - __uint_as_float(hb));
        }
    };

    float4 aR = ldA(0);
    float4 bR = *(const float4*)&W1[bk * 256 + hn0 + bn];
    stage(0, aR, bR);
    __syncthreads();

    int lane = t & 31, w = t >> 5;
    int wm = (w & 3) * 32, wn = (w >> 2) * 64;
    int grp = lane >> 2, quad = lane & 3;

    float acc[2][8][4];
#pragma unroll
    for (int i = 0; i < 2; i++)
#pragma unroll
        for (int j = 0; j < 8; j++)
#pragma unroll
            for (int k = 0; k < 4; k++) acc[i][j][k] = 0.f;

    for (int kt = 0; kt < 66; ++kt) {
        int cur = kt & 1;
        if (kt < 65) {
            aR = ldA((kt + 1) * 8);
            bR = *(const float4*)&W1[((kt + 1) * 8 + bk) * 256 + hn0 + bn];
        }
        uint32_t aH[2][4], aL[2][4];
#pragma unroll
        for (int mf = 0; mf < 2; mf++) {
            int r0 = wm + mf * 16 + grp, r1 = r0 + 8;
            aH[mf][0] = AsH[cur][quad][r0];
            aH[mf][1] = AsH[cur][quad][r1];
            aH[mf][2] = AsH[cur][quad + 4][r0];
            aH[mf][3] = AsH[cur][quad + 4][r1];
            aL[mf][0] = AsL[cur][quad][r0];
            aL[mf][1] = AsL[cur][quad][r1];
            aL[mf][2] = AsL[cur][quad + 4][r0];
            aL[mf][3] = AsL[cur][quad + 4][r1];
        }
#pragma unroll
        for (int nf = 0; nf < 8; nf++) {
            int nc = wn + nf * 8 + grp;
            uint32_t bH0 = BsH[cur][quad][nc], bH1 = BsH[cur][quad + 4][nc];
            uint32_t bL0 = BsL[cur][quad][nc], bL1 = BsL[cur][quad + 4][nc];
#pragma unroll
            for (int mf = 0; mf < 2; mf++) {
                mma8(acc[mf][nf], aH[mf], bH0, bH1);
                mma8(acc[mf][nf], aH[mf], bL0, bL1);
                mma8(acc[mf][nf], aL[mf], bH0, bH1);
            }
        }
        if (kt < 65) stage(cur ^ 1, aR, bR);
        __syncthreads();
    }

    // epilogue: bias + relu, write g_hidden
#pragma unroll
    for (int mf = 0; mf < 2; mf++) {
#pragma unroll
        for (int nf = 0; nf < 8; nf++) {
            int m = me0 + wm + mf * 16 + grp;
            int h = hn0 + wn + nf * 8 + quad * 2;
            float2 v0, v1;
            v0.x = fmaxf(acc[mf][nf][0] + b1[h + 0], 0.f);
            v0.y = fmaxf(acc[mf][nf][1] + b1[h + 1], 0.f);
            v1.x = fmaxf(acc[mf][nf][2] + b1[h + 0], 0.f);
            v1.y = fmaxf(acc[mf][nf][3] + b1[h + 1], 0.f);
            *(float2*)&g_hidden[(size_t)m * 256 + h] = v0;
            *(float2*)&g_hidden[(size_t)(m + 8) * 256 + h] = v1;
        }
    }
}

// ==================== GEMM2 (tensor, 3xTF32): cand = hidden @ W2 + b2 ====================
__global__ void __launch_bounds__(256)
k_gemm2(const float* __restrict__ W2, const float* __restrict__ b2) {
    __shared__ uint32_t AsH[2][8][136], AsL[2][8][136];
    __shared__ uint32_t BsH[2][8][136], BsL[2][8][136];
    int t = threadIdx.x;
    int me0 = blockIdx.x * 128;

    int am = t >> 1, ak = (t & 1) * 4;
    int bk = t >> 5, bn = (t & 31) * 4;

    auto stage = [&](int buf, float4 av, float4 bv) {
        float fa[4] = {av.x, av.y, av.z, av.w};
        float fb[4] = {bv.x, bv.y, bv.z, bv.w};
#pragma unroll
        for (int i = 0; i < 4; i++) {
            uint32_t h = f2tf(fa[i]);
            AsH[buf][ak + i][am] = h;
            AsL[buf][ak + i][am] = f2tf(fa[i] - __uint_as_float(h));
            uint32_t hb = f2tf(fb[i]);
            BsH[buf][bk][bn + i] = hb;
            BsL[buf][bk][bn + i] = f2tf(fb[i] - __uint_as_float(hb));
        }
    };

    float4 aR = *(const float4*)&g_hidden[(size_t)(me0 + am) * 256 + ak];
    float4 bR = *(const float4*)&W2[bk * 128 + bn];
    stage(0, aR, bR);
    __syncthreads();

    int lane = t & 31, w = t >> 5;
    int wm = (w & 3) * 32, wn = (w >> 2) * 64;
    int grp = lane >> 2, quad = lane & 3;

    float acc[2][8][4];
#pragma unroll
    for (int i = 0; i < 2; i++)
#pragma unroll
        for (int j = 0; j < 8; j++)
#pragma unroll
            for (int k = 0; k < 4; k++) acc[i][j][k] = 0.f;

    for (int kt = 0; kt < 32; ++kt) {
        int cur = kt & 1;
        if (kt < 31) {
            aR = *(const float4*)&g_hidden[(size_t)(me0 + am) * 256 + (kt + 1) * 8 + ak];
            bR = *(const float4*)&W2[((kt + 1) * 8 + bk) * 128 + bn];
        }
        uint32_t aH[2][4], aL[2][4];
#pragma unroll
        for (int mf = 0; mf < 2; mf++) {
            int r0 = wm + mf * 16 + grp, r1 = r0 + 8;
            aH[mf][0] = AsH[cur][quad][r0];
            aH[mf][1] = AsH[cur][quad][r1];
            aH[mf][2] = AsH[cur][quad + 4][r0];
            aH[mf][3] = AsH[cur][quad + 4][r1];
            aL[mf][0] = AsL[cur][quad][r0];
            aL[mf][1] = AsL[cur][quad][r1];
            aL[mf][2] = AsL[cur][quad + 4][r0];
            aL[mf][3] = AsL[cur][quad + 4][r1];
        }
#pragma unroll
        for (int nf = 0; nf < 8; nf++) {
            int nc = wn + nf * 8 + grp;
            uint32_t bH0 = BsH[cur][quad][nc], bH1 = BsH[cur][quad + 4][nc];
            uint32_t bL0 = BsL[cur][quad][nc], bL1 = BsL[cur][quad + 4][nc];
#pragma unroll
            for (int mf = 0; mf < 2; mf++) {
                mma8(acc[mf][nf], aH[mf], bH0, bH1);
                mma8(acc[mf][nf], aH[mf], bL0, bL1);
                mma8(acc[mf][nf], aL[mf], bH0, bH1);
            }
        }
        if (kt < 31) stage(cur ^ 1, aR, bR);
        __syncthreads();
    }

#pragma unroll
    for (int mf = 0; mf < 2; mf++) {
#pragma unroll
        for (int nf = 0; nf < 8; nf++) {
            int m = me0 + wm + mf * 16 + grp;
            int h = wn + nf * 8 + quad * 2;
            float2 v0, v1;
            v0.x = acc[mf][nf][0] + b2[h + 0];
            v0.y = acc[mf][nf][1] + b2[h + 1];
            v1.x = acc[mf][nf][2] + b2[h + 0];
            v1.y = acc[mf][nf][3] + b2[h + 1];
            *(float2*)&g_cand[(size_t)m * 128 + h] = v0;
            *(float2*)&g_cand[(size_t)(m + 8) * 128 + h] = v1;
        }
    }
}

// ---------------- gate + edge_feat + readout logits + segment max ----------------
__global__ void k_gate(const float* __restrict__ hef, const float* __restrict__ attr,
                       const int* __restrict__ ei, const int* __restrict__ batch,
                       const float* __restrict__ Wupd, const float* __restrict__ bupd,
                       const float* __restrict__ Wread, const float* __restrict__ bread,
                       float* __restrict__ out) {
    int warp = threadIdx.x >> 5, lane = threadIdx.x & 31;
    int e = blockIdx.x * 8 + warp;
    if (e >= NE) return;
    int r = ei[e], c = ei[NE + e];
    float4 cd = ((const float4*)g_cand)[e * 32 + lane];
    float4 hh = ((const float4*)hef)[e * 32 + lane];
    float4 wuc = *(const float4*)&Wupd[400 + lane * 4];
    float4 wuh = *(const float4*)&Wupd[272 + lane * 4];
    float p = dot4(cd, wuc) + dot4(hh, wuh);
    float4 a4 = make_float4(0.f, 0.f, 0.f, 0.f);
    if (lane < 4) {
        a4 = ((const float4*)attr)[e * 4 + lane];
        float4 wua = *(const float4*)&Wupd[256 + lane * 4];
        p += dot4(a4, wua);
    }
    p = wred(p);
    float gv = p + g_nproj[r * 8 + 2] + g_nproj[c * 8 + 3] + bupd[0];
    float g = 1.f / (1.f + expf(-gv));
    float4 ef;
    ef.x = fmaf(g, cd.x - hh.x, hh.x);
    ef.y = fmaf(g, cd.y - hh.y, hh.y);
    ef.z = fmaf(g, cd.z - hh.z, hh.z);
    ef.w = fmaf(g, cd.w - hh.w, hh.w);
    ((float4*)out)[e * 32 + lane] = ef;

    float4 wre = *(const float4*)&Wread[256 + lane * 4];
    float q = dot4(ef, wre);
    if (lane < 4) {
        float4 wra = *(const float4*)&Wread[384 + lane * 4];
        q += dot4(a4, wra);
    }
    q = wred(q);
    if (lane == 0) {
        float rl = q + g_nproj[r * 8 + 4] + g_nproj[c * 8 + 5] + bread[0];
        g_rlogit[e] = rl;
        atomicMaxF(&g_gmax[batch[r]], rl);
    }
}

// ---------------- readout exp + segment sum (smem aggregated) ----------------
__global__ void k_rexp(const int* __restrict__ ei, const int* __restrict__ batch) {
    __shared__ float ss[NG];
    int t = threadIdx.x;
    if (t < NG) ss[t] = 0.f;
    __syncthreads();
    int e = blockIdx.x * 256 + t;
    if (e < NE) {
        int gi = batch[ei[e]];
        float rw = expf(g_rlogit[e] - g_gmax[gi]);
        g_rw[e] = rw;
        atomicAdd(&ss[gi], rw);
    }
    __syncthreads();
    if (t < NG && ss[t] != 0.f) atomicAdd(&g_gsum[t], ss[t]);
}

// ---------------- readout scatter into graph_feat (smem 64x128 tile) ----------------
__global__ void k_rscatter(const int* __restrict__ ei, const int* __restrict__ batch,
                           const float* __restrict__ out) {
    __shared__ float sacc[NG * DE];   // 32 KB
    int t = threadIdx.x;
    for (int i = t; i < NG * DE; i += 256) sacc[i] = 0.f;
    __syncthreads();
    int warp = t >> 5, lane = t & 31;
    for (int e = blockIdx.x * 8 + warp; e < NE; e += gridDim.x * 8) {
        int gi = batch[ei[e]];
        float rn = g_rw[e] / (g_gsum[gi] + 1e-16f);
        float4 ef = ((const float4*)out)[e * 32 + lane];
        float* p = &sacc[gi * 128 + lane * 4];
        atomicAdd(p + 0, rn * ef.x);
        atomicAdd(p + 1, rn * ef.y);
        atomicAdd(p + 2, rn * ef.z);
        atomicAdd(p + 3, rn * ef.w);
    }
    __syncthreads();
    for (int i = t; i < NG * DE; i += 256)
        if (sacc[i] != 0.f) atomicAdd(&g_graphfeat[i], sacc[i]);
}

// ---------------- confidence ----------------
__global__ void k_conf(const float* __restrict__ Wscore, const float* __restrict__ bscore,
                       float* __restrict__ out) {
    int g = blockIdx.x, t = threadIdx.x;
    float v = g_graphfeat[g * 128 + t] * Wscore[t];
    v = wred(v);
    __shared__ float sm[4];
    if ((t & 31) == 0) sm[t >> 5] = v;
    __syncthreads();
    if (t == 0) {
        float s = sm[0] + sm[1] + sm[2] + sm[3] + bscore[0];
        out[(size_t)NE * DE + g] = 1.f / (1.f + expf(-s));
    }
}

// ---------------- launch ----------------
extern "C" void kernel_launch(void* const* d_in, const int* in_sizes, int n_in,
                              void* d_out, int out_size) {
    const float* x      = (const float*)d_in[0];
    const float* hef    = (const float*)d_in[1];
    const float* attr   = (const float*)d_in[2];
    const int*   ei     = (const int*)d_in[3];
    const int*   batch  = (const int*)d_in[4];
    // d_in[5] = num_graphs (compile-time NG)
    const float* Wagg   = (const float*)d_in[6];
    const float* bagg   = (const float*)d_in[7];
    const float* W1     = (const float*)d_in[8];
    const float* b1     = (const float*)d_in[9];
    const float* W2     = (const float*)d_in[10];
    const float* b2     = (const float*)d_in[11];
    const float* Wupd   = (const float*)d_in[12];
    const float* bupd   = (const float*)d_in[13];
    const float* Wread  = (const float*)d_in[14];
    const float* bread  = (const float*)d_in[15];
    const float* Wscore = (const float*)d_in[16];
    const float* bscore = (const float*)d_in[17];
    float* out = (float*)d_out;

    k_init<<<(NN * DE + 255) / 256, 256>>>();
    k_nodeproj<<<(NN + 7) / 8, 256>>>(x, Wagg, Wupd, Wread);
    k_agglogit<<<NE / 8, 256>>>(hef, attr, ei, Wagg, bagg);
    k_expw<<<NE / 256, 256>>>(ei);
    k_nscatter<<<NE / 8, 256>>>(hef, ei);
    k_gemm1<<<dim3(NE / 128, NH / 128), 256>>>(x, attr, ei, W1, b1);
    k_gemm2<<<NE / 128, 256>>>(W2, b2);
    k_gate<<<NE / 8, 256>>>(hef, attr, ei, batch, Wupd, bupd, Wread, bread, out);
    k_rexp<<<NE / 256, 256>>>(ei, batch);
    k_rscatter<<<296, 256>>>(ei, batch, out);
    k_conf<<<NG, 128>>>(Wscore, bscore, out);
}

// round 3
// speedup vs baseline: 1.8274x; 1.5990x over previous
#include <cuda_runtime.h>
#include <cuda_bf16.h>
#include <stdint.h>

#define NN 20000      // nodes
#define NE 320000     // edges
#define DN 128        // d_node
#define DE 128        // d_edge
#define DA 16         // d_attr
#define NH 256        // hidden
#define NG 64         // graphs
#define K1TOT 528

// ---------------- scratch ----------------
__device__ float g_nproj[NN * 8];
__device__ float g_logit[NE];
__device__ float g_w[NE];
__device__ float g_nmax[NN];
__device__ float g_nsum[NN];
__device__ float g_nodefeat[NN * DE];
__device__ float g_hidden[81920000];         // NE*NH fp32
__device__ float g_cand[40960000];           // NE*DE fp32
__device__ float g_rlogit[NE];
__device__ float g_rw[NE];
__device__ float g_gmax[NG];
__device__ float g_gsum[NG];
__device__ float g_graphfeat[NG * DE];

// ---------------- helpers ----------------
__device__ __forceinline__ float dot4(float4 a, float4 b) {
    return fmaf(a.x, b.x, fmaf(a.y, b.y, fmaf(a.z, b.z, a.w * b.w)));
}

__device__ __forceinline__ float wred(float v) {
    v += __shfl_xor_sync(0xffffffffu, v, 16);
    v += __shfl_xor_sync(0xffffffffu, v, 8);
    v += __shfl_xor_sync(0xffffffffu, v, 4);
    v += __shfl_xor_sync(0xffffffffu, v, 2);
    v += __shfl_xor_sync(0xffffffffu, v, 1);
    return v;
}

__device__ __forceinline__ void atomicMaxF(float* addr, float v) {
    int* ia = (int*)addr;
    int old = __float_as_int(*addr);
    while (__int_as_float(old) < v) {
        int prev = atomicCAS(ia, old, __float_as_int(v));
        if (prev == old) break;
        old = prev;
    }
}

// pack two floats' bf16-hi parts (f0 -> low half)
__device__ __forceinline__ uint32_t packhi(float f0, float f1) {
    __nv_bfloat162 h = __floats2bfloat162_rn(f0, f1);
    return *(uint32_t*)&h;
}
// residuals after hi split
__device__ __forceinline__ uint32_t packlo(float f0, float f1, uint32_t hi) {
    __nv_bfloat162 h = *(__nv_bfloat162*)&hi;
    float l0 = f0 - __bfloat162float(h.x);
    float l1 = f1 - __bfloat162float(h.y);
    __nv_bfloat162 l = __floats2bfloat162_rn(l0, l1);
    return *(uint32_t*)&l;
}

__device__ __forceinline__ void mma16(float* c, const uint32_t* a, uint32_t b0, uint32_t b1) {
    asm volatile("mma.sync.aligned.m16n8k16.row.col.f32.bf16.bf16.f32 "
        "{%0,%1,%2,%3}, {%4,%5,%6,%7}, {%8,%9}, {%0,%1,%2,%3};"
        : "+f"(c[0]), "+f"(c[1]), "+f"(c[2]), "+f"(c[3])
        : "r"(a[0]), "r"(a[1]), "r"(a[2]), "r"(a[3]), "r"(b0), "r"(b1));
}

// ---------------- init scratch ----------------
__global__ void k_init() {
    int i = blockIdx.x * 256 + threadIdx.x;
    if (i < NN * DE) g_nodefeat[i] = 0.f;
    if (i < NN) { g_nmax[i] = -1e30f; g_nsum[i] = 0.f; }
    if (i < NG * DE) g_graphfeat[i] = 0.f;
    if (i < NG) { g_gmax[i] = -1e30f; g_gsum[i] = 0.f; }
}

// ---------------- per-node scalar projections ----------------
__global__ void k_nodeproj(const float* __restrict__ x, const float* __restrict__ Wagg,
                           const float* __restrict__ Wupd, const float* __restrict__ Wread) {
    int warp = threadIdx.x >> 5, lane = threadIdx.x & 31;
    int n = blockIdx.x * 8 + warp;
    if (n >= NN) return;
    float4 xv = ((const float4*)x)[n * 32 + lane];
    const float4* wa = (const float4*)Wagg;
    const float4* wu = (const float4*)Wupd;
    const float4* wr = (const float4*)Wread;
    float s0 = dot4(xv, wa[lane]);
    float s1 = dot4(xv, wa[32 + lane]);
    float s2 = dot4(xv, wu[lane]);
    float s3 = dot4(xv, wu[32 + lane]);
    float s4 = dot4(xv, wr[lane]);
    float s5 = dot4(xv, wr[32 + lane]);
    s0 = wred(s0); s1 = wred(s1); s2 = wred(s2);
    s3 = wred(s3); s4 = wred(s4); s5 = wred(s5);
    if (lane == 0) {
        g_nproj[n * 8 + 0] = s0; g_nproj[n * 8 + 1] = s1;
        g_nproj[n * 8 + 2] = s2; g_nproj[n * 8 + 3] = s3;
        g_nproj[n * 8 + 4] = s4; g_nproj[n * 8 + 5] = s5;
    }
}

// ---------------- aggregation attention logits + segment max ----------------
__global__ void k_agglogit(const float* __restrict__ hef, const float* __restrict__ attr,
                           const int* __restrict__ ei, const float* __restrict__ Wagg,
                           const float* __restrict__ bagg) {
    int warp = threadIdx.x >> 5, lane = threadIdx.x & 31;
    int e = blockIdx.x * 8 + warp;
    if (e >= NE) return;
    int r = ei[e], c = ei[NE + e];
    float4 h4 = ((const float4*)hef)[e * 32 + lane];
    float4 wh = *(const float4*)&Wagg[272 + lane * 4];
    float p = dot4(h4, wh);
    if (lane < 4) {
        float4 a4 = ((const float4*)attr)[e * 4 + lane];
        float4 wa = *(const float4*)&Wagg[256 + lane * 4];
        p += dot4(a4, wa);
    }
    p = wred(p);
    if (lane == 0) {
        float logit = p + g_nproj[r * 8 + 0] + g_nproj[c * 8 + 1] + bagg[0];
        g_logit[e] = logit;
        atomicMaxF(&g_nmax[c], logit);
    }
}

// ---------------- exp + segment sum ----------------
__global__ void k_expw(const int* __restrict__ ei) {
    int e = blockIdx.x * 256 + threadIdx.x;
    if (e >= NE) return;
    int c = ei[NE + e];
    float w = expf(g_logit[e] - g_nmax[c]);
    g_w[e] = w;
    atomicAdd(&g_nsum[c], w);
}

// ---------------- normalize + scatter w*h into node_feat (vector red) ----------------
__global__ void k_nscatter(const float* __restrict__ hef, const int* __restrict__ ei) {
    int warp = threadIdx.x >> 5, lane = threadIdx.x & 31;
    int e = blockIdx.x * 8 + warp;
    if (e >= NE) return;
    int c = ei[NE + e];
    float wn = g_w[e] / (g_nsum[c] + 1e-16f);
    float4 h4 = ((const float4*)hef)[e * 32 + lane];
    float* p = &g_nodefeat[c * 128 + lane * 4];
    asm volatile("red.global.add.v4.f32 [%0], {%1,%2,%3,%4};"
        :: "l"(p), "f"(wn * h4.x), "f"(wn * h4.y), "f"(wn * h4.z), "f"(wn * h4.w)
        : "memory");
}

// ==================== GEMM1 (tensor, 3x bf16-split, m16n8k16) ====================
// Block tile 128x128, 8 warps 4(M)x2(N), warp tile 32x64, k-tile 16.
__global__ void __launch_bounds__(256)
k_gemm1(const float* __restrict__ x, const float* __restrict__ attr,
        const int* __restrict__ ei, const float* __restrict__ W1,
        const float* __restrict__ b1) {
    __shared__ uint32_t AsH[2][8][136], AsL[2][8][136];
    __shared__ uint32_t BsH[2][8][136], BsL[2][8][136];
    __shared__ int srol[128], scol[128];
    int t = threadIdx.x;
    int me0 = blockIdx.x * 128, hn0 = blockIdx.y * 128;
    if (t < 128) srol[t] = ei[me0 + t];
    else scol[t - 128] = ei[NE + me0 + t - 128];
    __syncthreads();

    int am = t >> 1, ak = (t & 1) * 8;     // A: row am, k = base+ak .. +7
    int bkp = t >> 5, bn = (t & 31) * 4;   // B: k-pair row bkp (rows 2bkp,2bkp+1), cols bn..+3

    auto ldA = [&](int k) -> float4 {
        if (k < 128) return *(const float4*)&x[srol[am] * 128 + k];
        if (k < 256) return *(const float4*)&g_nodefeat[srol[am] * 128 + (k - 128)];
        if (k < 384) return *(const float4*)&x[scol[am] * 128 + (k - 256)];
        if (k < 512) return *(const float4*)&g_nodefeat[scol[am] * 128 + (k - 384)];
        return *(const float4*)&attr[(me0 + am) * 16 + (k - 512)];
    };

    auto stage = [&](int buf, float4 a0, float4 a1, float4 r0, float4 r1) {
        int kp = ak >> 1;
        float fa[8] = {a0.x, a0.y, a0.z, a0.w, a1.x, a1.y, a1.z, a1.w};
#pragma unroll
        for (int i = 0; i < 4; i++) {
            uint32_t h = packhi(fa[2 * i], fa[2 * i + 1]);
            AsH[buf][kp + i][am] = h;
            AsL[buf][kp + i][am] = packlo(fa[2 * i], fa[2 * i + 1], h);
        }
        float f0[4] = {r0.x, r0.y, r0.z, r0.w};
        float f1[4] = {r1.x, r1.y, r1.z, r1.w};
#pragma unroll
        for (int i = 0; i < 4; i++) {
            uint32_t h = packhi(f0[i], f1[i]);
            BsH[buf][bkp][bn + i] = h;
            BsL[buf][bkp][bn + i] = packlo(f0[i], f1[i], h);
        }
    };

    float4 a0 = ldA(ak), a1 = ldA(ak + 4);
    float4 r0 = *(const float4*)&W1[(2 * bkp) * 256 + hn0 + bn];
    float4 r1 = *(const float4*)&W1[(2 * bkp + 1) * 256 + hn0 + bn];
    stage(0, a0, a1, r0, r1);
    __syncthreads();

    int lane = t & 31, w = t >> 5;
    int wm = (w & 3) * 32, wn = (w >> 2) * 64;
    int grp = lane >> 2, quad = lane & 3;

    float acc[2][8][4];
#pragma unroll
    for (int i = 0; i < 2; i++)
#pragma unroll
        for (int j = 0; j < 8; j++)
#pragma unroll
            for (int k = 0; k < 4; k++) acc[i][j][k] = 0.f;

    const int KT = K1TOT / 16;  // 33
    for (int kt = 0; kt < KT; ++kt) {
        int cur = kt & 1;
        if (kt < KT - 1) {
            int k0 = (kt + 1) * 16;
            a0 = ldA(k0 + ak); a1 = ldA(k0 + ak + 4);
            r0 = *(const float4*)&W1[(k0 + 2 * bkp) * 256 + hn0 + bn];
            r1 = *(const float4*)&W1[(k0 + 2 * bkp + 1) * 256 + hn0 + bn];
        }
        uint32_t aH[2][4], aL[2][4];
#pragma unroll
        for (int mf = 0; mf < 2; mf++) {
            int rr0 = wm + mf * 16 + grp, rr1 = rr0 + 8;
            aH[mf][0] = AsH[cur][quad][rr0];
            aH[mf][1] = AsH[cur][quad][rr1];
            aH[mf][2] = AsH[cur][quad + 4][rr0];
            aH[mf][3] = AsH[cur][quad + 4][rr1];
            aL[mf][0] = AsL[cur][quad][rr0];
            aL[mf][1] = AsL[cur][quad][rr1];
            aL[mf][2] = AsL[cur][quad + 4][rr0];
            aL[mf][3] = AsL[cur][quad + 4][rr1];
        }
#pragma unroll
        for (int nf = 0; nf < 8; nf++) {
            int nc = wn + nf * 8 + grp;
            uint32_t bH0 = BsH[cur][quad][nc], bH1 = BsH[cur][quad + 4][nc];
            uint32_t bL0 = BsL[cur][quad][nc], bL1 = BsL[cur][quad + 4][nc];
#pragma unroll
            for (int mf = 0; mf < 2; mf++) {
                mma16(acc[mf][nf], aH[mf], bH0, bH1);
                mma16(acc[mf][nf], aH[mf], bL0, bL1);
                mma16(acc[mf][nf], aL[mf], bH0, bH1);
            }
        }
        if (kt < KT - 1) stage(cur ^ 1, a0, a1, r0, r1);
        __syncthreads();
    }

#pragma unroll
    for (int mf = 0; mf < 2; mf++) {
#pragma unroll
        for (int nf = 0; nf < 8; nf++) {
            int m = me0 + wm + mf * 16 + grp;
            int h = hn0 + wn + nf * 8 + quad * 2;
            float2 v0, v1;
            v0.x = fmaxf(acc[mf][nf][0] + b1[h + 0], 0.f);
            v0.y = fmaxf(acc[mf][nf][1] + b1[h + 1], 0.f);
            v1.x = fmaxf(acc[mf][nf][2] + b1[h + 0], 0.f);
            v1.y = fmaxf(acc[mf][nf][3] + b1[h + 1], 0.f);
            *(float2*)&g_hidden[(size_t)m * 256 + h] = v0;
            *(float2*)&g_hidden[(size_t)(m + 8) * 256 + h] = v1;
        }
    }
}

// ==================== GEMM2 (tensor, 3x bf16-split): cand = hidden @ W2 + b2 ====================
__global__ void __launch_bounds__(256)
k_gemm2(const float* __restrict__ W2, const float* __restrict__ b2) {
    __shared__ uint32_t AsH[2][8][136], AsL[2][8][136];
    __shared__ uint32_t BsH[2][8][136], BsL[2][8][136];
    int t = threadIdx.x;
    int me0 = blockIdx.x * 128;

    int am = t >> 1, ak = (t & 1) * 8;
    int bkp = t >> 5, bn = (t & 31) * 4;

    auto stage = [&](int buf, float4 a0, float4 a1, float4 r0, float4 r1) {
        int kp = ak >> 1;
        float fa[8] = {a0.x, a0.y, a0.z, a0.w, a1.x, a1.y, a1.z, a1.w};
#pragma unroll
        for (int i = 0; i < 4; i++) {
            uint32_t h = packhi(fa[2 * i], fa[2 * i + 1]);
            AsH[buf][kp + i][am] = h;
            AsL[buf][kp + i][am] = packlo(fa[2 * i], fa[2 * i + 1], h);
        }
        float f0[4] = {r0.x, r0.y, r0.z, r0.w};
        float f1[4] = {r1.x, r1.y, r1.z, r1.w};
#pragma unroll
        for (int i = 0; i < 4; i++) {
            uint32_t h = packhi(f0[i], f1[i]);
            BsH[buf][bkp][bn + i] = h;
            BsL[buf][bkp][bn + i] = packlo(f0[i], f1[i], h);
        }
    };

    float4 a0 = *(const float4*)&g_hidden[(size_t)(me0 + am) * 256 + ak];
    float4 a1 = *(const float4*)&g_hidden[(size_t)(me0 + am) * 256 + ak + 4];
    float4 r0 = *(const float4*)&W2[(2 * bkp) * 128 + bn];
    float4 r1 = *(const float4*)&W2[(2 * bkp + 1) * 128 + bn];
    stage(0, a0, a1, r0, r1);
    __syncthreads();

    int lane = t & 31, w = t >> 5;
    int wm = (w & 3) * 32, wn = (w >> 2) * 64;
    int grp = lane >> 2, quad = lane & 3;

    float acc[2][8][4];
#pragma unroll
    for (int i = 0; i < 2; i++)
#pragma unroll
        for (int j = 0; j < 8; j++)
#pragma unroll
            for (int k = 0; k < 4; k++) acc[i][j][k] = 0.f;

    const int KT = NH / 16;  // 16
    for (int kt = 0; kt < KT; ++kt) {
        int cur = kt & 1;
        if (kt < KT - 1) {
            int k0 = (kt + 1) * 16;
            a0 = *(const float4*)&g_hidden[(size_t)(me0 + am) * 256 + k0 + ak];
            a1 = *(const float4*)&g_hidden[(size_t)(me0 + am) * 256 + k0 + ak + 4];
            r0 = *(const float4*)&W2[(k0 + 2 * bkp) * 128 + bn];
            r1 = *(const float4*)&W2[(k0 + 2 * bkp + 1) * 128 + bn];
        }
        uint32_t aH[2][4], aL[2][4];
#pragma unroll
        for (int mf = 0; mf < 2; mf++) {
            int rr0 = wm + mf * 16 + grp, rr1 = rr0 + 8;
            aH[mf][0] = AsH[cur][quad][rr0];
            aH[mf][1] = AsH[cur][quad][rr1];
            aH[mf][2] = AsH[cur][quad + 4][rr0];
            aH[mf][3] = AsH[cur][quad + 4][rr1];
            aL[mf][0] = AsL[cur][quad][rr0];
            aL[mf][1] = AsL[cur][quad][rr1];
            aL[mf][2] = AsL[cur][quad + 4][rr0];
            aL[mf][3] = AsL[cur][quad + 4][rr1];
        }
#pragma unroll
        for (int nf = 0; nf < 8; nf++) {
            int nc = wn + nf * 8 + grp;
            uint32_t bH0 = BsH[cur][quad][nc], bH1 = BsH[cur][quad + 4][nc];
            uint32_t bL0 = BsL[cur][quad][nc], bL1 = BsL[cur][quad + 4][nc];
#pragma unroll
            for (int mf = 0; mf < 2; mf++) {
                mma16(acc[mf][nf], aH[mf], bH0, bH1);
                mma16(acc[mf][nf], aH[mf], bL0, bL1);
                mma16(acc[mf][nf], aL[mf], bH0, bH1);
            }
        }
        if (kt < KT - 1) stage(cur ^ 1, a0, a1, r0, r1);
        __syncthreads();
    }

#pragma unroll
    for (int mf = 0; mf < 2; mf++) {
#pragma unroll
        for (int nf = 0; nf < 8; nf++) {
            int m = me0 + wm + mf * 16 + grp;
            int h = wn + nf * 8 + quad * 2;
            float2 v0, v1;
            v0.x = acc[mf][nf][0] + b2[h + 0];
            v0.y = acc[mf][nf][1] + b2[h + 1];
            v1.x = acc[mf][nf][2] + b2[h + 0];
            v1.y = acc[mf][nf][3] + b2[h + 1];
            *(float2*)&g_cand[(size_t)m * 128 + h] = v0;
            *(float2*)&g_cand[(size_t)(m + 8) * 128 + h] = v1;
        }
    }
}

// ---------------- gate + edge_feat + readout logits + segment max ----------------
__global__ void k_gate(const float* __restrict__ hef, const float* __restrict__ attr,
                       const int* __restrict__ ei, const int* __restrict__ batch,
                       const float* __restrict__ Wupd, const float* __restrict__ bupd,
                       const float* __restrict__ Wread, const float* __restrict__ bread,
                       float* __restrict__ out) {
    int warp = threadIdx.x >> 5, lane = threadIdx.x & 31;
    int e = blockIdx.x * 8 + warp;
    if (e >= NE) return;
    int r = ei[e], c = ei[NE + e];
    float4 cd = ((const float4*)g_cand)[e * 32 + lane];
    float4 hh = ((const float4*)hef)[e * 32 + lane];
    float4 wuc = *(const float4*)&Wupd[400 + lane * 4];
    float4 wuh = *(const float4*)&Wupd[272 + lane * 4];
    float p = dot4(cd, wuc) + dot4(hh, wuh);
    float4 a4 = make_float4(0.f, 0.f, 0.f, 0.f);
    if (lane < 4) {
        a4 = ((const float4*)attr)[e * 4 + lane];
        float4 wua = *(const float4*)&Wupd[256 + lane * 4];
        p += dot4(a4, wua);
    }
    p = wred(p);
    float gv = p + g_nproj[r * 8 + 2] + g_nproj[c * 8 + 3] + bupd[0];
    float g = 1.f / (1.f + expf(-gv));
    float4 ef;
    ef.x = fmaf(g, cd.x - hh.x, hh.x);
    ef.y = fmaf(g, cd.y - hh.y, hh.y);
    ef.z = fmaf(g, cd.z - hh.z, hh.z);
    ef.w = fmaf(g, cd.w - hh.w, hh.w);
    ((float4*)out)[e * 32 + lane] = ef;

    float4 wre = *(const float4*)&Wread[256 + lane * 4];
    float q = dot4(ef, wre);
    if (lane < 4) {
        float4 wra = *(const float4*)&Wread[384 + lane * 4];
        q += dot4(a4, wra);
    }
    q = wred(q);
    if (lane == 0) {
        float rl = q + g_nproj[r * 8 + 4] + g_nproj[c * 8 + 5] + bread[0];
        g_rlogit[e] = rl;
        atomicMaxF(&g_gmax[batch[r]], rl);
    }
}

// ---------------- readout exp + segment sum ----------------
__global__ void k_rexp(const int* __restrict__ ei, const int* __restrict__ batch) {
    __shared__ float ss[NG];
    int t = threadIdx.x;
    if (t < NG) ss[t] = 0.f;
    __syncthreads();
    int e = blockIdx.x * 256 + t;
    if (e < NE) {
        int gi = batch[ei[e]];
        float rw = expf(g_rlogit[e] - g_gmax[gi]);
        g_rw[e] = rw;
        atomicAdd(&ss[gi], rw);
    }
    __syncthreads();
    if (t < NG && ss[t] != 0.f) atomicAdd(&g_gsum[t], ss[t]);
}

// ---------------- readout scatter ----------------
__global__ void k_rscatter(const int* __restrict__ ei, const int* __restrict__ batch,
                           const float* __restrict__ out) {
    __shared__ float sacc[NG * DE];
    int t = threadIdx.x;
    for (int i = t; i < NG * DE; i += 256) sacc[i] = 0.f;
    __syncthreads();
    int warp = t >> 5, lane = t & 31;
    for (int e = blockIdx.x * 8 + warp; e < NE; e += gridDim.x * 8) {
        int gi = batch[ei[e]];
        float rn = g_rw[e] / (g_gsum[gi] + 1e-16f);
        float4 ef = ((const float4*)out)[e * 32 + lane];
        float* p = &sacc[gi * 128 + lane * 4];
        atomicAdd(p + 0, rn * ef.x);
        atomicAdd(p + 1, rn * ef.y);
        atomicAdd(p + 2, rn * ef.z);
        atomicAdd(p + 3, rn * ef.w);
    }
    __syncthreads();
    for (int i = t; i < NG * DE; i += 256)
        if (sacc[i] != 0.f) atomicAdd(&g_graphfeat[i], sacc[i]);
}

// ---------------- confidence ----------------
__global__ void k_conf(const float* __restrict__ Wscore, const float* __restrict__ bscore,
                       float* __restrict__ out) {
    int g = blockIdx.x, t = threadIdx.x;
    float v = g_graphfeat[g * 128 + t] * Wscore[t];
    v = wred(v);
    __shared__ float sm[4];
    if ((t & 31) == 0) sm[t >> 5] = v;
    __syncthreads();
    if (t == 0) {
        float s = sm[0] + sm[1] + sm[2] + sm[3] + bscore[0];
        out[(size_t)NE * DE + g] = 1.f / (1.f + expf(-s));
    }
}

// ---------------- launch ----------------
extern "C" void kernel_launch(void* const* d_in, const int* in_sizes, int n_in,
                              void* d_out, int out_size) {
    const float* x      = (const float*)d_in[0];
    const float* hef    = (const float*)d_in[1];
    const float* attr   = (const float*)d_in[2];
    const int*   ei     = (const int*)d_in[3];
    const int*   batch  = (const int*)d_in[4];
    const float* Wagg   = (const float*)d_in[6];
    const float* bagg   = (const float*)d_in[7];
    const float* W1     = (const float*)d_in[8];
    const float* b1     = (const float*)d_in[9];
    const float* W2     = (const float*)d_in[10];
    const float* b2     = (const float*)d_in[11];
    const float* Wupd   = (const float*)d_in[12];
    const float* bupd   = (const float*)d_in[13];
    const float* Wread  = (const float*)d_in[14];
    const float* bread  = (const float*)d_in[15];
    const float* Wscore = (const float*)d_in[16];
    const float* bscore = (const float*)d_in[17];
    float* out = (float*)d_out;

    k_init<<<(NN * DE + 255) / 256, 256>>>();
    k_nodeproj<<<(NN + 7) / 8, 256>>>(x, Wagg, Wupd, Wread);
    k_agglogit<<<NE / 8, 256>>>(hef, attr, ei, Wagg, bagg);
    k_expw<<<NE / 256, 256>>>(ei);
    k_nscatter<<<NE / 8, 256>>>(hef, ei);
    k_gemm1<<<dim3(NE / 128, NH / 128), 256>>>(x, attr, ei, W1, b1);
    k_gemm2<<<NE / 128, 256>>>(W2, b2);
    k_gate<<<NE / 8, 256>>>(hef, attr, ei, batch, Wupd, bupd, Wread, bread, out);
    k_rexp<<<NE / 256, 256>>>(ei, batch);
    k_rscatter<<<296, 256>>>(ei, batch, out);
    k_conf<<<NG, 128>>>(Wscore, bscore, out);
}